// round 6
// baseline (speedup 1.0000x reference)
#include <cuda_runtime.h>
#include <cstdint>
#include <climits>

#define DIM    768
#define KC     2048
#define NROWS  16384
#define BM     64
#define BN     256
#define BK     64                // bytes (s8) per chunk
#define CHUNKS (DIM / BK)        // 12
#define NTILE  (KC / BN)         // 8
#define TOT    (NTILE * CHUNKS)  // 96
#define STAGE  20480             // A 4KB + B 16KB
#define QSCALE 131072.0f
#define QWIN   400               // candidate window in quanta (~3.05e-3)
#define SZ     22.0f
#define SE     260096.0f         // 127 * 2048

__device__ float g_enorm[KC];
__device__ float g_zsum[NROWS];
__device__ float g_loss;
__device__ signed char g_z8[(size_t)NROWS * DIM];
__device__ signed char g_e8[(size_t)KC * DIM];
__device__ short g_si[(size_t)NROWS * KC];     // 64 MiB quantized scores

static __device__ __forceinline__ uint32_t smem_u32(const void* p) {
    uint32_t a;
    asm("{ .reg .u64 t; cvta.to.shared.u64 t, %1; cvt.u32.u64 %0, t; }" : "=r"(a) : "l"(p));
    return a;
}
#define CP_ASYNC16(dst, src) \
    asm volatile("cp.async.cg.shared.global [%0], [%1], 16;" :: "r"(dst), "l"(src))
#define CP_COMMIT() asm volatile("cp.async.commit_group;" ::: "memory")
#define LDMX4(r, addr) \
    asm volatile("ldmatrix.sync.aligned.m8n8.x4.shared.b16 {%0,%1,%2,%3}, [%4];" \
        : "=r"((r)[0]), "=r"((r)[1]), "=r"((r)[2]), "=r"((r)[3]) : "r"(addr))
#define MMA16832(d, a, b0_, b1_) \
    asm volatile("mma.sync.aligned.m16n8k32.row.col.s32.s8.s8.s32 " \
        "{%0,%1,%2,%3}, {%4,%5,%6,%7}, {%8,%9}, {%0,%1,%2,%3};" \
        : "+r"((d)[0]), "+r"((d)[1]), "+r"((d)[2]), "+r"((d)[3]) \
        : "r"((a)[0]), "r"((a)[1]), "r"((a)[2]), "r"((a)[3]), "r"(b0_), "r"(b1_))

// -------- fused fp32->s8 quantize + exact fp32 row squared-norm (warp/row) --------
__global__ void prep_kernel(const float* __restrict__ src,
                            signed char* __restrict__ dst,
                            float* __restrict__ norms, float qs, int nrows) {
    int w    = (blockIdx.x * blockDim.x + threadIdx.x) >> 5;
    int lane = threadIdx.x & 31;
    if (w >= nrows) return;
    const float2* s2 = (const float2*)(src + (size_t)w * DIM);
    unsigned short* d2 = (unsigned short*)(dst + (size_t)w * DIM);
    float acc = 0.f;
#pragma unroll
    for (int j = 0; j < DIM / 64; j++) {        // 12
        float2 v = s2[lane + j * 32];
        acc = fmaf(v.x, v.x, fmaf(v.y, v.y, acc));
        int q0 = max(-127, min(127, __float2int_rn(v.x * qs)));
        int q1 = max(-127, min(127, __float2int_rn(v.y * qs)));
        d2[lane + j * 32] = (unsigned short)((q0 & 0xFF) | ((q1 & 0xFF) << 8));
    }
#pragma unroll
    for (int o = 16; o > 0; o >>= 1) acc += __shfl_down_sync(0xffffffffu, acc, o);
    if (lane == 0) norms[w] = acc;
}

__global__ void zero_kernel() { g_loss = 0.f; }

// -------- pass 1: s8 IMMA approx-score GEMM -> int16 score grid --------
// 256 CTAs x 256 thr. CTA: 64 rows x 2048 codes. Warps 2x4, warp tile 32x64.
__global__ __launch_bounds__(256, 2)
void vq_pass1_kernel() {
    extern __shared__ char smem_raw[];
    const uint32_t sb = (smem_u32(smem_raw) + 127u) & ~127u;
    const int tid  = threadIdx.x;
    const int lane = tid & 31;
    const int w    = tid >> 5;
    const int wr   = w >> 2;    // 0..1  rows 32 each
    const int wc   = w & 3;     // 0..3  cols 64 each
    const int rowBase = blockIdx.x * BM;
    const float CF = 2.0f * QSCALE / (SZ * SE);

    // ---- cp.async: 5 x 16B per thread per stage (A 256 granules, B 1024) ----
    uint32_t sdst[5];
    const signed char* gptr[5];
    bool isB[5];
#pragma unroll
    for (int i = 0; i < 5; i++) {
        int idx = i * 256 + tid;
        if (idx < 256) {
            int r = idx >> 2, g = idx & 3;
            sdst[i] = (uint32_t)(r * 64 + ((g ^ ((r >> 1) & 3)) << 4));
            gptr[i] = g_z8 + (size_t)(rowBase + r) * DIM + g * 16;
            isB[i] = false;
        } else {
            int j = idx - 256;
            int r = j >> 2, g = j & 3;
            sdst[i] = (uint32_t)(4096 + r * 64 + ((g ^ ((r >> 1) & 3)) << 4));
            gptr[i] = g_e8 + (size_t)r * DIM + g * 16;
            isB[i] = true;
        }
    }

    // ---- ldmatrix lane addressing (s8 m16k32 / n8k32 fragments) ----
    const int arow = lane & 15;
    const int agr  = lane >> 4;                          // kbyte half
    const int brow = (lane & 7) + ((lane >> 4) & 1) * 8; // code within 16
    const int bgr  = (lane >> 3) & 1;
    uint32_t a_rt[2]; int a_sw[2];
#pragma unroll
    for (int mt = 0; mt < 2; mt++) {
        int r = wr * 32 + mt * 16 + arow;
        a_rt[mt] = r * 64; a_sw[mt] = (r >> 1) & 3;
    }
    uint32_t b_rt[4]; int b_sw[4];
#pragma unroll
    for (int nb = 0; nb < 4; nb++) {
        int r = wc * 64 + nb * 16 + brow;
        b_rt[nb] = r * 64; b_sw[nb] = (r >> 1) & 3;
    }

    int acc[2][8][4];
#pragma unroll
    for (int mt = 0; mt < 2; mt++)
#pragma unroll
        for (int nt = 0; nt < 8; nt++)
#pragma unroll
            for (int q = 0; q < 4; q++) acc[mt][nt][q] = 0;

    auto issue = [&](int ct, int c, int buf) {
        uint32_t st = sb + buf * STAGE;
        size_t k0 = (size_t)c * BK;
        size_t bo = (size_t)ct * BN * DIM + k0;
#pragma unroll
        for (int i = 0; i < 5; i++) {
            const signed char* src = gptr[i] + (isB[i] ? bo : k0);
            CP_ASYNC16(st + sdst[i], src);
        }
        CP_COMMIT();
    };

    issue(0, 0, 0);
    issue(0, 1, 1);
    issue(0, 2, 2);
    int cct = 0, ccc = 0;

    for (int s = 0; s < TOT; s++) {
        if (s >= TOT - 3) asm volatile("cp.async.wait_group 0;" ::: "memory");
        else              asm volatile("cp.async.wait_group 2;" ::: "memory");
        __syncthreads();
        int nx = s + 3;
        if (nx < TOT) issue(nx / CHUNKS, nx % CHUNKS, nx & 3);

        const uint32_t Ab = sb + (s & 3) * STAGE;
        const uint32_t Bb = Ab + 4096;

#pragma unroll
        for (int ks = 0; ks < 2; ks++) {                 // two k32 steps
            const int g0 = ks * 2;
            uint32_t ah[8], bh[16];
#pragma unroll
            for (int mt = 0; mt < 2; mt++) {
                uint32_t ad = Ab + a_rt[mt] + (uint32_t)(((g0 + agr) ^ a_sw[mt]) << 4);
                LDMX4(&ah[mt * 4], ad);
            }
#pragma unroll
            for (int nb = 0; nb < 4; nb++) {
                uint32_t bd = Bb + b_rt[nb] + (uint32_t)(((g0 + bgr) ^ b_sw[nb]) << 4);
                LDMX4(&bh[nb * 4], bd);
            }
#pragma unroll
            for (int mt = 0; mt < 2; mt++)
#pragma unroll
                for (int nt = 0; nt < 8; nt++) {
                    const int bo_ = (nt >> 1) * 4 + (nt & 1) * 2;
                    MMA16832(acc[mt][nt], &ah[mt * 4], bh[bo_], bh[bo_ + 1]);
                }
        }

        // ---- tile end: dequantize -> int16 approx-score store ----
        if (ccc == CHUNKS - 1) {
#pragma unroll
            for (int nt = 0; nt < 8; nt++) {
                int cb = cct * BN + wc * 64 + nt * 8 + (lane & 3) * 2;
                float eq0 = __ldg(&g_enorm[cb])     * QSCALE;
                float eq1 = __ldg(&g_enorm[cb + 1]) * QSCALE;
#pragma unroll
                for (int mt = 0; mt < 2; mt++)
#pragma unroll
                    for (int h = 0; h < 2; h++) {
                        int q0 = __float2int_rn(eq0 - CF * (float)acc[mt][nt][h * 2]);
                        int q1 = __float2int_rn(eq1 - CF * (float)acc[mt][nt][h * 2 + 1]);
                        q0 = max(-32767, min(32767, q0));
                        q1 = max(-32767, min(32767, q1));
                        int row0 = rowBase + wr * 32 + mt * 16 + h * 8 + (lane >> 2);
                        *(short2*)&g_si[(size_t)row0 * KC + cb] =
                            make_short2((short)q0, (short)q1);
                        acc[mt][nt][h * 2] = 0;
                        acc[mt][nt][h * 2 + 1] = 0;
                    }
            }
        }
        if (++ccc == CHUNKS) { ccc = 0; ++cct; }
    }
}

// -------- refine-all: scan + exact argmin + gather + loss (warp/row) --------
__global__ __launch_bounds__(256)
void refine_kernel(const float* __restrict__ z, const float* __restrict__ emb,
                   float* __restrict__ ids_out, float* __restrict__ zq) {
    __shared__ float redl[8];
    const int w    = threadIdx.x >> 5;
    const int lane = threadIdx.x & 31;
    const int r    = blockIdx.x * 8 + w;

    const short* qr = g_si + (size_t)r * KC;
    const float zr = g_zsum[r];

    // z row in registers (exact fp32)
    float zreg[24];
    const float* zrow = z + (size_t)r * DIM;
#pragma unroll
    for (int j = 0; j < 24; j++) zreg[j] = zrow[lane + j * 32];

    // min scan over quantized scores
    int qmin = INT_MAX;
    const short2* q2 = (const short2*)qr;
#pragma unroll 8
    for (int j = 0; j < 32; j++) {
        short2 p = q2[lane + j * 32];
        qmin = min(qmin, min((int)p.x, (int)p.y));
    }
#pragma unroll
    for (int o = 16; o > 0; o >>= 1)
        qmin = min(qmin, __shfl_xor_sync(0xffffffffu, qmin, o));
    const int qthr = qmin + QWIN;

    // candidates -> exact fp32 score with reference rounding, first-index ties
    float best = 3.4e38f;
    int   bi   = INT_MAX;
    for (int k = 0; k < 64; k++) {
        int c = k * 32 + lane;
        unsigned mask = __ballot_sync(0xffffffffu, (int)qr[c] <= qthr);
        while (mask) {
            int l = __ffs(mask) - 1;
            mask &= mask - 1;
            int cc = k * 32 + l;
            const float* erow = emb + (size_t)cc * DIM;
            float d = 0.f;
#pragma unroll
            for (int j = 0; j < 24; j++) d = fmaf(zreg[j], erow[lane + j * 32], d);
#pragma unroll
            for (int o = 16; o > 0; o >>= 1) d += __shfl_xor_sync(0xffffffffu, d, o);
            float se = (zr + g_enorm[cc]) - 2.0f * d;   // 2*d exact -> ref rounding
            if (se < best || (se == best && cc < bi)) { best = se; bi = cc; }
        }
    }

    // gather z_q + commitment-loss partial
    const float* erow = emb + (size_t)bi * DIM;
    float* qrow = zq + (size_t)r * DIM;
    float lacc = 0.f;
#pragma unroll
    for (int j = 0; j < 24; j++) {
        float q = erow[lane + j * 32];
        qrow[lane + j * 32] = q;
        float dd = zreg[j] - q;
        lacc = fmaf(dd, dd, lacc);
    }
#pragma unroll
    for (int o = 16; o > 0; o >>= 1) lacc += __shfl_down_sync(0xffffffffu, lacc, o);
    if (lane == 0) {
        ids_out[r] = (float)bi;
        redl[w] = lacc;
    }
    __syncthreads();
    if (threadIdx.x == 0) {
        float t = 0.f;
#pragma unroll
        for (int i = 0; i < 8; i++) t += redl[i];
        atomicAdd(&g_loss, t);
    }
}

__global__ void finalize_kernel(float* __restrict__ loss_out) {
    *loss_out = 0.25f * (g_loss / (float)((long long)NROWS * DIM));
}

// ---------------- launch ----------------
extern "C" void kernel_launch(void* const* d_in, const int* in_sizes, int n_in,
                              void* d_out, int out_size) {
    (void)in_sizes; (void)n_in; (void)out_size;
    const float* z   = (const float*)d_in[0];
    const float* emb = (const float*)d_in[1];
    float* out   = (float*)d_out;
    float* zq    = out;                              // [NROWS*DIM]
    float* idsf  = out + (size_t)NROWS * DIM;        // [NROWS]
    float* lossp = idsf + NROWS;                     // [1]

    signed char *z8_p, *e8_p;
    float *zsum_p, *enorm_p;
    cudaGetSymbolAddress((void**)&z8_p, g_z8);
    cudaGetSymbolAddress((void**)&e8_p, g_e8);
    cudaGetSymbolAddress((void**)&zsum_p, g_zsum);
    cudaGetSymbolAddress((void**)&enorm_p, g_enorm);

    const int VQ_SMEM = 4 * STAGE + 128;            // 82048
    cudaFuncSetAttribute(vq_pass1_kernel, cudaFuncAttributeMaxDynamicSharedMemorySize, VQ_SMEM);

    prep_kernel<<<NROWS / 8, 256>>>(z, z8_p, zsum_p, SZ, NROWS);
    prep_kernel<<<KC / 8, 256>>>(emb, e8_p, enorm_p, SE, KC);
    zero_kernel<<<1, 1>>>();
    vq_pass1_kernel<<<NROWS / BM, 256, VQ_SMEM>>>();
    refine_kernel<<<NROWS / 8, 256>>>(z, emb, idsf, zq);
    finalize_kernel<<<1, 1>>>(lossp);
}

// round 7
// speedup vs baseline: 2.1313x; 2.1313x over previous
#include <cuda_runtime.h>
#include <cuda_bf16.h>
#include <cstdint>
#include <climits>

#define DIM    768
#define KC     2048
#define NROWS  16384
#define BM     64
#define BN     256
#define BK     64                // bf16 elems per chunk = 128 B/row
#define CHUNKS (DIM / BK)        // 12
#define NTILE  (KC / BN)         // 8
#define TOT    (NTILE * CHUNKS)  // 96
#define STAGE  40960             // A 8KB + B 32KB
#define MARGIN 5e-4f
#define QSCALE 131072.0f
#define QTHR_Q 85                // refine window in quanta (~6.5e-4)

__device__ float g_enorm[KC];
__device__ float g_zsum[NROWS];
__device__ float g_loss;
__device__ int   g_nwork;
__device__ int   g_work[NROWS];
__device__ __nv_bfloat16 g_zhi[(size_t)NROWS * DIM];
__device__ __nv_bfloat16 g_ehi[(size_t)KC * DIM];
__device__ short g_si[(size_t)NROWS * KC];     // 64 MiB quantized scores

static __device__ __forceinline__ uint32_t smem_u32(const void* p) {
    uint32_t a;
    asm("{ .reg .u64 t; cvta.to.shared.u64 t, %1; cvt.u32.u64 %0, t; }" : "=r"(a) : "l"(p));
    return a;
}
#define CP_ASYNC16(dst, src) \
    asm volatile("cp.async.cg.shared.global [%0], [%1], 16;" :: "r"(dst), "l"(src))
#define CP_COMMIT() asm volatile("cp.async.commit_group;" ::: "memory")
#define LDMX4(r, addr) \
    asm volatile("ldmatrix.sync.aligned.m8n8.x4.shared.b16 {%0,%1,%2,%3}, [%4];" \
        : "=r"((r)[0]), "=r"((r)[1]), "=r"((r)[2]), "=r"((r)[3]) : "r"(addr))
#define MMA16816(d, a, b0_, b1_) \
    asm volatile("mma.sync.aligned.m16n8k16.row.col.f32.bf16.bf16.f32 " \
        "{%0,%1,%2,%3}, {%4,%5,%6,%7}, {%8,%9}, {%0,%1,%2,%3};" \
        : "+f"((d)[0]), "+f"((d)[1]), "+f"((d)[2]), "+f"((d)[3]) \
        : "r"((a)[0]), "r"((a)[1]), "r"((a)[2]), "r"((a)[3]), "r"(b0_), "r"(b1_))

// -------- fused fp32->bf16 convert + exact fp32 row squared-norm (warp/row) --------
__global__ void prep_kernel(const float* __restrict__ src,
                            __nv_bfloat16* __restrict__ dst,
                            float* __restrict__ norms, int nrows) {
    int w    = (blockIdx.x * blockDim.x + threadIdx.x) >> 5;
    int lane = threadIdx.x & 31;
    if (w >= nrows) return;
    const float2* s2 = (const float2*)(src + (size_t)w * DIM);
    __nv_bfloat162* d2 = (__nv_bfloat162*)(dst + (size_t)w * DIM);
    float acc = 0.f;
#pragma unroll
    for (int j = 0; j < DIM / 64; j++) {
        float2 v = s2[lane + j * 32];
        acc = fmaf(v.x, v.x, fmaf(v.y, v.y, acc));
        d2[lane + j * 32] = __halves2bfloat162(__float2bfloat16_rn(v.x),
                                               __float2bfloat16_rn(v.y));
    }
#pragma unroll
    for (int o = 16; o > 0; o >>= 1) acc += __shfl_down_sync(0xffffffffu, acc, o);
    if (lane == 0) norms[w] = acc;
}

__global__ void zero_kernel() { g_loss = 0.f; g_nwork = 0; }

// -------- pass 1: bf16 HMMA approx GEMM + in-kernel top-2 + int16 scores --------
// 256 CTAs x 256 thr. CTA: 64 rows x 2048 codes. Warps 2x4, warp tile 32x64.
// BK=64: 96 iterations, 64 MMAs per iteration between barriers.
__global__ __launch_bounds__(256, 2)
void vq_pass1_kernel(float* __restrict__ ids_out) {
    extern __shared__ char smem_raw[];
    const uint32_t sb = (smem_u32(smem_raw) + 127u) & ~127u;
    const int tid  = threadIdx.x;
    const int lane = tid & 31;
    const int w    = tid >> 5;
    const int wr   = w >> 2;    // 0..1  rows 32 each
    const int wc   = w & 3;     // 0..3  cols 64 each
    const int rowBase = blockIdx.x * BM;

    // ---- cp.async: strength-reduced addressing ----
    // A granules: idx = tid, tid+256 -> rows t>>3, t>>3+32, granule t&7.
    // B granules: idx = tid + i*256  -> rows t>>3 + k*32 (k=0..7), granule t&7.
    const int gr  = tid >> 3;          // base row 0..31
    const int gg  = tid & 7;           // granule 0..7
    const uint32_t swx = (uint32_t)((gg ^ (gr & 7)) << 4);
    const uint32_t da  = (uint32_t)(gr * 128) + swx;           // A dst base
    const uint32_t db  = 8192u + (uint32_t)(gr * 128) + swx;   // B dst base
    const __nv_bfloat16* baseA = g_zhi + (size_t)(rowBase + gr) * DIM + gg * 8;
    const __nv_bfloat16* baseB = g_ehi + (size_t)gr * DIM + gg * 8;

    // ---- ldmatrix lane addressing ----
    const int arow = lane & 15;
    const int agr  = lane >> 4;
    const int brow = (lane & 7) + ((lane >> 4) & 1) * 8;
    const int bgr  = (lane >> 3) & 1;
    uint32_t a_rt[2]; int a_sw[2];
#pragma unroll
    for (int mt = 0; mt < 2; mt++) {
        int r = wr * 32 + mt * 16 + arow;
        a_rt[mt] = r * 128; a_sw[mt] = r & 7;
    }
    uint32_t b_rt[4]; int b_sw[4];
#pragma unroll
    for (int nb = 0; nb < 4; nb++) {
        int r = wc * 64 + nb * 16 + brow;
        b_rt[nb] = r * 128; b_sw[nb] = r & 7;
    }

    float acc[2][8][4];
#pragma unroll
    for (int mt = 0; mt < 2; mt++)
#pragma unroll
        for (int nt = 0; nt < 8; nt++)
#pragma unroll
            for (int q = 0; q < 4; q++) acc[mt][nt][q] = 0.f;

    // per-thread top-2 per row-slot (slot = mt*2+h)
    float v1[4], v2[4], zr4[4];
    int   i1[4];
#pragma unroll
    for (int sl = 0; sl < 4; sl++) {
        v1[sl] = 3.4e38f; v2[sl] = 3.4e38f; i1[sl] = 0;
        zr4[sl] = g_zsum[rowBase + wr * 32 + (sl >> 1) * 16 + (sl & 1) * 8 + (lane >> 2)];
    }

    auto issue = [&](int ct, int c, int buf) {
        const uint32_t st = sb + (uint32_t)buf * STAGE;
        const __nv_bfloat16* pa = baseA + c * BK;
        CP_ASYNC16(st + da, pa);
        CP_ASYNC16(st + da + 4096u, pa + 32 * DIM);
        const __nv_bfloat16* pb = baseB + (size_t)ct * BN * DIM + c * BK;
#pragma unroll
        for (int k = 0; k < 8; k++)
            CP_ASYNC16(st + db + (uint32_t)k * 4096u, pb + (size_t)k * 32 * DIM);
        CP_COMMIT();
    };

    issue(0, 0, 0);
    int cct = 0, ccc = 0;

    for (int s = 0; s < TOT; s++) {
        asm volatile("cp.async.wait_group 0;" ::: "memory");
        __syncthreads();
        int nx = s + 1;
        if (nx < TOT) issue(nx / CHUNKS, nx % CHUNKS, nx & 1);

        const uint32_t Ab = sb + (uint32_t)(s & 1) * STAGE;
        const uint32_t Bb = Ab + 8192u;

#pragma unroll
        for (int ks = 0; ks < 4; ks++) {
            const int g0 = ks * 2;
            uint32_t ah[8], bh[16];
#pragma unroll
            for (int mt = 0; mt < 2; mt++) {
                uint32_t ad = Ab + a_rt[mt] + (uint32_t)(((g0 + agr) ^ a_sw[mt]) << 4);
                LDMX4(&ah[mt * 4], ad);
            }
#pragma unroll
            for (int nb = 0; nb < 4; nb++) {
                uint32_t bd = Bb + b_rt[nb] + (uint32_t)(((g0 + bgr) ^ b_sw[nb]) << 4);
                LDMX4(&bh[nb * 4], bd);
            }
#pragma unroll
            for (int mt = 0; mt < 2; mt++)
#pragma unroll
                for (int nt = 0; nt < 8; nt++) {
                    const int bo_ = (nt >> 1) * 4 + (nt & 1) * 2;
                    MMA16816(acc[mt][nt], &ah[mt * 4], bh[bo_], bh[bo_ + 1]);
                }
        }

        // ---- tile end: top-2 update + int16 score store ----
        if (ccc == CHUNKS - 1) {
#pragma unroll
            for (int nt = 0; nt < 8; nt++) {
                int cb = cct * BN + wc * 64 + nt * 8 + (lane & 3) * 2;
                float e0 = __ldg(&g_enorm[cb]);
                float e1 = __ldg(&g_enorm[cb + 1]);
#pragma unroll
                for (int mt = 0; mt < 2; mt++)
#pragma unroll
                    for (int h = 0; h < 2; h++) {
                        const int sl = mt * 2 + h;
                        float d0 = acc[mt][nt][h * 2], d1 = acc[mt][nt][h * 2 + 1];
                        // reference rounding: fl(fl(zsum+enorm) - 2*dot)
                        float s0 = (zr4[sl] + e0) - 2.0f * d0;
                        float s1 = (zr4[sl] + e1) - 2.0f * d1;
                        if (s0 < v1[sl]) { v2[sl] = v1[sl]; v1[sl] = s0; i1[sl] = cb; }
                        else if (s0 < v2[sl]) v2[sl] = s0;
                        if (s1 < v1[sl]) { v2[sl] = v1[sl]; v1[sl] = s1; i1[sl] = cb + 1; }
                        else if (s1 < v2[sl]) v2[sl] = s1;
                        int q0 = __float2int_rn(fminf(fmaxf((e0 - 2.0f * d0) * QSCALE, -32767.f), 32767.f));
                        int q1 = __float2int_rn(fminf(fmaxf((e1 - 2.0f * d1) * QSCALE, -32767.f), 32767.f));
                        int row0 = rowBase + wr * 32 + mt * 16 + h * 8 + (lane >> 2);
                        *(short2*)&g_si[(size_t)row0 * KC + cb] =
                            make_short2((short)q0, (short)q1);
                        acc[mt][nt][h * 2] = 0.f;
                        acc[mt][nt][h * 2 + 1] = 0.f;
                    }
            }
        }
        if (++ccc == CHUNKS) { ccc = 0; ++cct; }
    }

    // ---- cross-thread top-2 merge (first-index ties) ----
#pragma unroll
    for (int off = 1; off <= 2; off <<= 1) {
#pragma unroll
        for (int sl = 0; sl < 4; sl++) {
            float ov1 = __shfl_xor_sync(0xffffffffu, v1[sl], off);
            float ov2 = __shfl_xor_sync(0xffffffffu, v2[sl], off);
            int   oi1 = __shfl_xor_sync(0xffffffffu, i1[sl], off);
            if (ov1 < v1[sl] || (ov1 == v1[sl] && oi1 < i1[sl])) {
                v2[sl] = fminf(v1[sl], ov2); v1[sl] = ov1; i1[sl] = oi1;
            } else {
                v2[sl] = fminf(ov1, v2[sl]);
            }
        }
    }
    __syncthreads();                 // stage buffers dead; reuse for reduction
    float* rv1 = (float*)smem_raw;
    float* rv2 = rv1 + 256;
    int*   ri1 = (int*)(rv2 + 256);
    if ((lane & 3) == 0) {
#pragma unroll
        for (int sl = 0; sl < 4; sl++) {
            int rl = wr * 32 + (sl >> 1) * 16 + (sl & 1) * 8 + (lane >> 2);
            rv1[rl * 4 + wc] = v1[sl];
            rv2[rl * 4 + wc] = v2[sl];
            ri1[rl * 4 + wc] = i1[sl];
        }
    }
    __syncthreads();
    if (tid < BM) {
        float b1 = rv1[tid * 4], b2 = rv2[tid * 4];
        int   bi = ri1[tid * 4];
#pragma unroll
        for (int t = 1; t < 4; t++) {
            float o1 = rv1[tid * 4 + t], o2 = rv2[tid * 4 + t];
            int   oi = ri1[tid * 4 + t];
            if (o1 < b1 || (o1 == b1 && oi < bi)) { b2 = fminf(b1, o2); b1 = o1; bi = oi; }
            else b2 = fminf(o1, b2);
        }
        ids_out[rowBase + tid] = (float)bi;
        if (b2 <= b1 + MARGIN) {
            int k = atomicAdd(&g_nwork, 1);
            g_work[k] = rowBase + tid;
        }
    }
}

// -------- refine: ambiguous rows only (warp per row) --------
__global__ __launch_bounds__(256)
void refine_kernel(const float* __restrict__ z, const float* __restrict__ emb,
                   float* __restrict__ ids_out) {
    const int nwork = g_nwork;
    const int lane  = threadIdx.x & 31;
    const int wg0   = (blockIdx.x * blockDim.x + threadIdx.x) >> 5;
    const int wstr  = (gridDim.x * blockDim.x) >> 5;
    for (int wi = wg0; wi < nwork; wi += wstr) {
        const int r = g_work[wi];
        const short* qr = g_si + (size_t)r * KC;
        const float zr = g_zsum[r];
        int qmin = INT_MAX;
        const short2* q2 = (const short2*)qr;
#pragma unroll 8
        for (int j = 0; j < 32; j++) {
            short2 p = q2[lane + j * 32];
            qmin = min(qmin, min((int)p.x, (int)p.y));
        }
#pragma unroll
        for (int o = 16; o > 0; o >>= 1)
            qmin = min(qmin, __shfl_xor_sync(0xffffffffu, qmin, o));
        const int qthr = qmin + QTHR_Q;

        float zreg[24];
        const float* zrow = z + (size_t)r * DIM;
#pragma unroll
        for (int j = 0; j < 24; j++) zreg[j] = zrow[lane + j * 32];

        float best = 3.4e38f;
        int   bi   = INT_MAX;
        for (int k = 0; k < 64; k++) {
            int c = k * 32 + lane;
            unsigned mask = __ballot_sync(0xffffffffu, (int)qr[c] <= qthr);
            while (mask) {
                int l = __ffs(mask) - 1;
                mask &= mask - 1;
                int cc = k * 32 + l;
                const float* erow = emb + (size_t)cc * DIM;
                float d = 0.f;
#pragma unroll
                for (int j = 0; j < 24; j++) d = fmaf(zreg[j], erow[lane + j * 32], d);
#pragma unroll
                for (int o = 16; o > 0; o >>= 1) d += __shfl_xor_sync(0xffffffffu, d, o);
                float se = (zr + g_enorm[cc]) - 2.0f * d;   // reference rounding
                if (se < best || (se == best && cc < bi)) { best = se; bi = cc; }
            }
        }
        if (lane == 0) ids_out[r] = (float)bi;
    }
}

// -------- gather z_q + commitment loss (warp per row) --------
__global__ __launch_bounds__(256)
void gather_loss_kernel(const float* __restrict__ z, const float* __restrict__ emb,
                        const float* __restrict__ idsf, float* __restrict__ zq) {
    __shared__ float redl[8];
    const int w    = threadIdx.x >> 5;
    const int lane = threadIdx.x & 31;
    const int r    = blockIdx.x * 8 + w;
    const int id   = (int)idsf[r];
    const float* zrow = z + (size_t)r * DIM;
    const float* erow = emb + (size_t)id * DIM;
    float* qrow = zq + (size_t)r * DIM;
    float lacc = 0.f;
#pragma unroll
    for (int j = 0; j < 24; j++) {
        float q  = erow[lane + j * 32];
        float zv = zrow[lane + j * 32];
        qrow[lane + j * 32] = q;
        float dd = zv - q;
        lacc = fmaf(dd, dd, lacc);
    }
#pragma unroll
    for (int o = 16; o > 0; o >>= 1) lacc += __shfl_down_sync(0xffffffffu, lacc, o);
    if (lane == 0) redl[w] = lacc;
    __syncthreads();
    if (threadIdx.x == 0) {
        float t = 0.f;
#pragma unroll
        for (int i = 0; i < 8; i++) t += redl[i];
        atomicAdd(&g_loss, t);
    }
}

__global__ void finalize_kernel(float* __restrict__ loss_out) {
    *loss_out = 0.25f * (g_loss / (float)((long long)NROWS * DIM));
}

// ---------------- launch ----------------
extern "C" void kernel_launch(void* const* d_in, const int* in_sizes, int n_in,
                              void* d_out, int out_size) {
    (void)in_sizes; (void)n_in; (void)out_size;
    const float* z   = (const float*)d_in[0];
    const float* emb = (const float*)d_in[1];
    float* out   = (float*)d_out;
    float* zq    = out;                              // [NROWS*DIM]
    float* idsf  = out + (size_t)NROWS * DIM;        // [NROWS]
    float* lossp = idsf + NROWS;                     // [1]

    __nv_bfloat16 *zhi_p, *ehi_p;
    float *zsum_p, *enorm_p;
    cudaGetSymbolAddress((void**)&zhi_p, g_zhi);
    cudaGetSymbolAddress((void**)&ehi_p, g_ehi);
    cudaGetSymbolAddress((void**)&zsum_p, g_zsum);
    cudaGetSymbolAddress((void**)&enorm_p, g_enorm);

    const int VQ_SMEM = 2 * STAGE + 128;            // 82048
    cudaFuncSetAttribute(vq_pass1_kernel, cudaFuncAttributeMaxDynamicSharedMemorySize, VQ_SMEM);

    prep_kernel<<<NROWS / 8, 256>>>(z, zhi_p, zsum_p, NROWS);
    prep_kernel<<<KC / 8, 256>>>(emb, ehi_p, enorm_p, KC);
    zero_kernel<<<1, 1>>>();
    vq_pass1_kernel<<<NROWS / BM, 256, VQ_SMEM>>>(idsf);
    refine_kernel<<<512, 256>>>(z, emb, idsf);
    gather_loss_kernel<<<NROWS / 8, 256>>>(z, emb, idsf, zq);
    finalize_kernel<<<1, 1>>>(lossp);
}